// round 10
// baseline (speedup 1.0000x reference)
#include <cuda_runtime.h>
#include <cstdint>

#define B_ 8
#define N_ 10000
#define C_ 80
#define K_ 8
#define THR 0.5f
#define T2  0.99f            // collection threshold: ~100 candidates/class
#define NMS_NEG -1e9f
#define CAP 256
#define NBLK (B_ * C_)       // 640

typedef unsigned long long u64;

// Scratch (allocation-free rule: __device__ globals; zero-initialized; every
// launch restores all counters to zero => graph-replay deterministic)
__device__ u64    g_cand[NBLK * CAP];
__device__ int    g_ccnt[NBLK * 32];      // 128B stride per counter (atomics)
__device__ float  g_sel_score[NBLK * K_];
__device__ float4 g_sel_box  [NBLK * K_];
__device__ int    g_barrier[B_ * 32];     // 128B stride per batch counter
__device__ int    g_done;

// key = (score_bits, N-n): max-key == (max score, lowest n). Valid scores are
// positive floats (uint order == float order); 0 = empty sentinel.
__device__ __forceinline__ u64 mkey(float v, int n) {
    return (((u64)__float_as_uint(v)) << 32) | (unsigned)(N_ - n);
}

__device__ __forceinline__ bool sup_iou(float4 a, float4 q) {
    float ih = fmaxf(fminf(a.z, q.z) - fmaxf(a.x, q.x), 0.0f);
    float iw = fmaxf(fminf(a.w, q.w) - fmaxf(a.y, q.y), 0.0f);
    float inter = ih * iw;
    float uni = (a.z - a.x) * (a.w - a.y) + (q.z - q.x) * (q.w - q.y) - inter;
    return inter / fmaxf(uni, 1e-9f) > 0.5f;
}

// ---------------------------------------------------------------------------
// ONE kernel, grid 640 x 256 thr, __launch_bounds__(256,5): all blocks are
// wave-1 resident (148*5=740 >= 640) so the spin barrier cannot deadlock.
//  Phase A: block (b,c) streams rows [125c,125c+125) of batch b (40KB
//           coalesced, streaming hint); appends keys >T2 per class.
//  Barrier: per-batch arrive + NANOSLEEP-backoff spin (80 arrivals) — keeps
//           waiters off the LSU/L2 while late blocks still stream.
//  Phase B: warp-0 register greedy NMS over <=256 keys (redux pops, batched
//           box prefetch, warp-parallel IoU). Exact fallback if thin/overflow.
//  Ticket:  last block: register top-8 per batch (warp = batch) + cleanup.
// Output (f32): boxes[8][8][4] | scores[8][8] | classes[8][8] | valid[8]
// ---------------------------------------------------------------------------
__global__ __launch_bounds__(256, 5) void nms_all(
    const float* __restrict__ boxes, const float* __restrict__ scores,
    float* __restrict__ out)
{
    __shared__ float4 selbox[K_];
    __shared__ float  selsc[K_];
    __shared__ int    sel_n[K_];
    __shared__ int    sh_nsel, sh_tick, sh_cnt;

    const int tid  = threadIdx.x;
    const int lane = tid & 31;
    const int blk  = blockIdx.x;
    const int b    = blk / C_;
    const int c    = blk % C_;           // doubles as phase-A slice id

    // ================= Phase A: stream slice + collect =================
    {
        const float4* sp = reinterpret_cast<const float4*>(scores)
                         + (size_t)b * 200000 + c * 2500;
        const int cbase = b * C_;
        #pragma unroll
        for (int k = 0; k < 10; k++) {               // 2500 = 9*256 + 196
            int i = tid + (k << 8);
            if (i < 2500) {
                float4 v = __ldcs(sp + i);           // stream, no reuse
                int n  = c * 125 + i / 20;           // global box row
                int c0 = (i % 20) * 4;               // class of v.x
                if (v.x > T2) { int p = atomicAdd(&g_ccnt[(cbase+c0  )*32], 1); if (p < CAP) g_cand[(cbase+c0  )*CAP+p] = mkey(v.x, n); }
                if (v.y > T2) { int p = atomicAdd(&g_ccnt[(cbase+c0+1)*32], 1); if (p < CAP) g_cand[(cbase+c0+1)*CAP+p] = mkey(v.y, n); }
                if (v.z > T2) { int p = atomicAdd(&g_ccnt[(cbase+c0+2)*32], 1); if (p < CAP) g_cand[(cbase+c0+2)*CAP+p] = mkey(v.z, n); }
                if (v.w > T2) { int p = atomicAdd(&g_ccnt[(cbase+c0+3)*32], 1); if (p < CAP) g_cand[(cbase+c0+3)*CAP+p] = mkey(v.w, n); }
            }
        }
    }
    __syncthreads();

    // ===== per-batch barrier: arrive, then backoff-spin (no L2 hammering) ===
    if (tid == 0) {
        __threadfence();
        int seen = atomicAdd(&g_barrier[b * 32], 1) + 1;
        if (seen < C_) {
            volatile int* bp = &g_barrier[b * 32];
            do { __nanosleep(256); } while (*bp < C_);
        }
        __threadfence();                  // acquire
        sh_cnt = g_ccnt[blk * 32];
        g_ccnt[blk * 32] = 0;             // self-clean for next replay
    }
    __syncthreads();

    // ================= Phase B: warp-0 register NMS ====================
    const int  cnt = sh_cnt;
    const int  m   = (cnt > CAP) ? 0 : cnt;   // overflow -> exact fallback

    if (tid < 32) {
        const float4* bxp = reinterpret_cast<const float4*>(boxes) + (size_t)b * N_;

        u64 k[8];
        #pragma unroll
        for (int j = 0; j < 8; j++) {
            int idx = lane + (j << 5);
            k[j] = (idx < m) ? __ldg(&g_cand[blk * CAP + idx]) : 0ULL;
        }

        int  nsel = 0;
        bool exhausted = (m == 0);
        while (nsel < K_ && !exhausted) {
            float4 myb = make_float4(0.f, 0.f, 0.f, 0.f);
            float  mysc = 0.f;
            int    myn  = 0;
            int    npop = 0;
            for (int p = 0; p < 8; p++) {
                u64 g = k[0];
                #pragma unroll
                for (int j = 1; j < 8; j++) if (k[j] > g) g = k[j];
                unsigned hi = (unsigned)(g >> 32);
                unsigned bh = __reduce_max_sync(0xffffffffu, hi);
                if (bh == 0u) { exhausted = true; break; }
                unsigned lo = (hi == bh) ? (unsigned)g : 0u;
                unsigned bl = __reduce_max_sync(0xffffffffu, lo);
                u64 gbest = (((u64)bh) << 32) | bl;
                if (lane == p) {                       // record + prefetch box
                    mysc = __uint_as_float(bh);
                    myn  = N_ - (int)bl;
                    myb  = __ldg(bxp + myn);
                }
                #pragma unroll
                for (int j = 0; j < 8; j++) if (k[j] == gbest) k[j] = 0;  // kill
                npop++;
            }

            for (int q = 0; q < npop && nsel < K_; q++) {
                float4 bb;
                bb.x = __shfl_sync(0xffffffffu, myb.x, q);
                bb.y = __shfl_sync(0xffffffffu, myb.y, q);
                bb.z = __shfl_sync(0xffffffffu, myb.z, q);
                bb.w = __shfl_sync(0xffffffffu, myb.w, q);
                float scq = __shfl_sync(0xffffffffu, mysc, q);
                int   nq  = __shfl_sync(0xffffffffu, myn, q);
                bool sup = (lane < nsel) ? sup_iou(bb, selbox[lane]) : false;
                if (!__ballot_sync(0xffffffffu, sup)) {
                    if (lane == 0) {
                        selbox[nsel] = bb; selsc[nsel] = scq; sel_n[nsel] = nq;
                    }
                    nsel++;
                    __syncwarp();
                }
            }
        }

        // ---- exact fallback (probability ~0 on this data) ----
        if (nsel < K_) {
            const float* scp = scores + (size_t)b * N_ * C_ + c;
            while (nsel < K_) {
                u64 best = 0;
                for (int n = lane; n < N_; n += 32) {
                    float v = __ldg(scp + (size_t)n * C_);
                    if (v > THR) {
                        bool excl = false;
                        for (int j = 0; j < nsel; j++) if (sel_n[j] == n) excl = true;
                        if (!excl) {
                            float4 bb = __ldg(bxp + n);
                            for (int j = 0; j < nsel; j++)
                                if (sup_iou(bb, selbox[j])) { excl = true; break; }
                        }
                        if (!excl) { u64 kk = mkey(v, n); if (kk > best) best = kk; }
                    }
                }
                #pragma unroll
                for (int off = 16; off > 0; off >>= 1) {
                    u64 ob = __shfl_down_sync(0xffffffffu, best, off);
                    if (ob > best) best = ob;
                }
                best = __shfl_sync(0xffffffffu, best, 0);
                if ((unsigned)(best >> 32) == 0u) break;
                int nn = N_ - (int)(best & 0xffffffffu);
                if (lane == 0) {
                    selbox[nsel] = __ldg(bxp + nn);
                    selsc[nsel]  = __uint_as_float((unsigned)(best >> 32));
                    sel_n[nsel]  = nn;
                }
                nsel++;
                __syncwarp();
            }
        }
        if (lane == 0) sh_nsel = nsel;
    }
    __syncthreads();

    if (tid < K_) {
        int o = blk * K_ + tid;
        int v = (tid < sh_nsel);
        g_sel_score[o] = v ? selsc[tid] : NMS_NEG;   // invalid -> NEG (< THR)
        float4 z = make_float4(0.f, 0.f, 0.f, 0.f);
        g_sel_box[o] = v ? selbox[tid] : z;
    }
    __threadfence();
    __syncthreads();
    if (tid == 0) sh_tick = atomicAdd(&g_done, 1);
    __syncthreads();
    if (sh_tick != NBLK - 1) return;
    __threadfence();

    // ======== fused final top-8 (last block): register-based, warp=batch ====
    {
        const int wb = tid >> 5;              // 8 warps, one batch each
        const int base = wb * C_ * K_;
        // key = (score_bits, 2047-j): max == (max score, lowest flat index j)
        u64 kk[20];
        #pragma unroll
        for (int q = 0; q < 20; q++) {        // j = lane + 32q, coalesced
            int j = lane + (q << 5);
            float v = g_sel_score[base + j];
            kk[q] = (v > THR)
                  ? ((((u64)__float_as_uint(v)) << 32) | (unsigned)(2047 - j))
                  : 0ULL;
        }
        int vcnt = 0;
        for (int k = 0; k < K_; k++) {
            u64 g = kk[0];
            #pragma unroll
            for (int q = 1; q < 20; q++) if (kk[q] > g) g = kk[q];
            unsigned hi = (unsigned)(g >> 32);
            unsigned bh = __reduce_max_sync(0xffffffffu, hi);
            float* ob = out + wb * 32 + k * 4;
            if (bh != 0u) {
                unsigned lo = (hi == bh) ? (unsigned)g : 0u;
                unsigned bl = __reduce_max_sync(0xffffffffu, lo);
                u64 gbest = (((u64)bh) << 32) | bl;
                #pragma unroll
                for (int q = 0; q < 20; q++) if (kk[q] == gbest) kk[q] = 0;
                int j = 2047 - (int)bl;
                if (lane == 0) {
                    float4 bb = g_sel_box[base + j];
                    ob[0] = fminf(fmaxf(bb.x, 0.f), 1.f);
                    ob[1] = fminf(fmaxf(bb.y, 0.f), 1.f);
                    ob[2] = fminf(fmaxf(bb.z, 0.f), 1.f);
                    ob[3] = fminf(fmaxf(bb.w, 0.f), 1.f);
                    out[B_ * 32 + wb * 8 + k] = __uint_as_float(bh);
                    out[B_ * 40 + wb * 8 + k] = (float)(j >> 3);   // class = j // K
                }
                vcnt++;
            } else if (lane == 0) {
                ob[0] = ob[1] = ob[2] = ob[3] = 0.f;
                out[B_ * 32 + wb * 8 + k] = 0.f;
                out[B_ * 40 + wb * 8 + k] = 0.f;
            }
        }
        if (lane == 0) out[B_ * 48 + wb] = (float)vcnt;
    }
    __syncthreads();
    if (tid == 0) {                       // self-clean for next graph replay
        g_done = 0;
        #pragma unroll
        for (int i = 0; i < B_; i++) g_barrier[i * 32] = 0;
    }
}

extern "C" void kernel_launch(void* const* d_in, const int* in_sizes, int n_in,
                              void* d_out, int out_size)
{
    const float* boxes  = (const float*)d_in[0];
    const float* scores = (const float*)d_in[1];
    if (n_in >= 2 && in_sizes[0] > in_sizes[1]) {   // defensive input order
        const float* t = boxes; boxes = scores; scores = t;
    }
    nms_all<<<NBLK, 256>>>(boxes, scores, (float*)d_out);
}

// round 11
// speedup vs baseline: 1.0430x; 1.0430x over previous
#include <cuda_runtime.h>
#include <cstdint>

#define B_ 8
#define N_ 10000
#define C_ 80
#define K_ 8
#define THR 0.5f
#define T2  0.99f            // collection threshold: ~100 candidates/class
#define NMS_NEG -1e9f
#define CAP 256
#define NBLK (B_ * C_)       // 640

typedef unsigned long long u64;

// Scratch (allocation-free rule: __device__ globals; zero-initialized; every
// launch restores all counters to zero => graph-replay deterministic)
__device__ u64    g_cand[NBLK * CAP];
__device__ int    g_ccnt[NBLK * 32];      // 128B stride per counter (atomics)
__device__ float  g_sel_score[NBLK * K_];
__device__ float4 g_sel_box  [NBLK * K_];
__device__ int    g_barrier[B_ * 32];     // 128B stride per batch counter
__device__ int    g_done;

// key = (score_bits, N-n): max-key == (max score, lowest n). Valid scores are
// positive floats (uint order == float order); 0 = empty sentinel.
__device__ __forceinline__ u64 mkey(float v, int n) {
    return (((u64)__float_as_uint(v)) << 32) | (unsigned)(N_ - n);
}

__device__ __forceinline__ bool sup_iou(float4 a, float4 q) {
    float ih = fmaxf(fminf(a.z, q.z) - fmaxf(a.x, q.x), 0.0f);
    float iw = fmaxf(fminf(a.w, q.w) - fmaxf(a.y, q.y), 0.0f);
    float inter = ih * iw;
    float uni = (a.z - a.x) * (a.w - a.y) + (q.z - q.x) * (q.w - q.y) - inter;
    return inter / fmaxf(uni, 1e-9f) > 0.5f;
}

// ---------------------------------------------------------------------------
// ONE kernel, grid 640 x 256 thr, __launch_bounds__(256,5): 40.2KB smem and
// <=51 regs => 5 blocks/SM => all 640 blocks wave-1 resident (148*5=740), so
// the spin barrier cannot deadlock.
//  Phase A: cp.async ALL ten 16B copies per thread into smem (full MLP, no
//           data regs), wait once, process from smem; append keys >T2/class.
//  Barrier: per-batch arrive + plain volatile spin (80 arrivals).
//  Phase B: warp-0 register greedy NMS over <=256 keys (redux pops, batched
//           box prefetch, warp-parallel IoU). Exact fallback if thin/overflow.
//  Ticket:  last block: register top-8 per batch (warp = batch) + cleanup.
// Output (f32): boxes[8][8][4] | scores[8][8] | classes[8][8] | valid[8]
// ---------------------------------------------------------------------------
__global__ __launch_bounds__(256, 5) void nms_all(
    const float* __restrict__ boxes, const float* __restrict__ scores,
    float* __restrict__ out)
{
    __shared__ float4 sbuf[2500];         // 40 KB slice buffer
    __shared__ float4 selbox[K_];
    __shared__ float  selsc[K_];
    __shared__ int    sel_n[K_];
    __shared__ int    sh_nsel, sh_tick, sh_cnt;

    const int tid  = threadIdx.x;
    const int lane = tid & 31;
    const int blk  = blockIdx.x;
    const int b    = blk / C_;
    const int c    = blk % C_;           // doubles as phase-A slice id

    // ===== Phase A1: issue ALL copies (cp.async.cg -> guaranteed MLP=10) ====
    {
        const float4* sp = reinterpret_cast<const float4*>(scores)
                         + (size_t)b * 200000 + c * 2500;
        #pragma unroll
        for (int k = 0; k < 10; k++) {               // 2500 = 9*256 + 196
            int i = tid + (k << 8);
            if (i < 2500) {
                unsigned saddr = (unsigned)__cvta_generic_to_shared(&sbuf[i]);
                asm volatile("cp.async.cg.shared.global [%0], [%1], 16;\n"
                             :: "r"(saddr), "l"(sp + i));
            }
        }
        asm volatile("cp.async.commit_group;\n" ::: "memory");
        asm volatile("cp.async.wait_group 0;\n" ::: "memory");
    }

    // ===== Phase A2: process own elements from smem (no block sync needed) ==
    {
        const int cbase = b * C_;
        #pragma unroll
        for (int k = 0; k < 10; k++) {
            int i = tid + (k << 8);
            if (i < 2500) {
                float4 v = sbuf[i];
                int n  = c * 125 + i / 20;           // global box row
                int c0 = (i % 20) * 4;               // class of v.x
                if (v.x > T2) { int p = atomicAdd(&g_ccnt[(cbase+c0  )*32], 1); if (p < CAP) g_cand[(cbase+c0  )*CAP+p] = mkey(v.x, n); }
                if (v.y > T2) { int p = atomicAdd(&g_ccnt[(cbase+c0+1)*32], 1); if (p < CAP) g_cand[(cbase+c0+1)*CAP+p] = mkey(v.y, n); }
                if (v.z > T2) { int p = atomicAdd(&g_ccnt[(cbase+c0+2)*32], 1); if (p < CAP) g_cand[(cbase+c0+2)*CAP+p] = mkey(v.z, n); }
                if (v.w > T2) { int p = atomicAdd(&g_ccnt[(cbase+c0+3)*32], 1); if (p < CAP) g_cand[(cbase+c0+3)*CAP+p] = mkey(v.w, n); }
            }
        }
    }
    __syncthreads();

    // ===== per-batch barrier: arrive + plain spin (R9-proven) ===============
    if (tid == 0) {
        __threadfence();
        atomicAdd(&g_barrier[b * 32], 1);
        volatile int* bp = &g_barrier[b * 32];
        while (*bp < C_) { }
        __threadfence();                  // acquire
        sh_cnt = g_ccnt[blk * 32];
        g_ccnt[blk * 32] = 0;             // self-clean for next replay
    }
    __syncthreads();

    // ================= Phase B: warp-0 register NMS ====================
    const int  cnt = sh_cnt;
    const int  m   = (cnt > CAP) ? 0 : cnt;   // overflow -> exact fallback

    if (tid < 32) {
        const float4* bxp = reinterpret_cast<const float4*>(boxes) + (size_t)b * N_;

        u64 k[8];
        #pragma unroll
        for (int j = 0; j < 8; j++) {
            int idx = lane + (j << 5);
            k[j] = (idx < m) ? __ldg(&g_cand[blk * CAP + idx]) : 0ULL;
        }

        int  nsel = 0;
        bool exhausted = (m == 0);
        while (nsel < K_ && !exhausted) {
            float4 myb = make_float4(0.f, 0.f, 0.f, 0.f);
            float  mysc = 0.f;
            int    myn  = 0;
            int    npop = 0;
            for (int p = 0; p < 8; p++) {
                u64 g = k[0];
                #pragma unroll
                for (int j = 1; j < 8; j++) if (k[j] > g) g = k[j];
                unsigned hi = (unsigned)(g >> 32);
                unsigned bh = __reduce_max_sync(0xffffffffu, hi);
                if (bh == 0u) { exhausted = true; break; }
                unsigned lo = (hi == bh) ? (unsigned)g : 0u;
                unsigned bl = __reduce_max_sync(0xffffffffu, lo);
                u64 gbest = (((u64)bh) << 32) | bl;
                if (lane == p) {                       // record + prefetch box
                    mysc = __uint_as_float(bh);
                    myn  = N_ - (int)bl;
                    myb  = __ldg(bxp + myn);
                }
                #pragma unroll
                for (int j = 0; j < 8; j++) if (k[j] == gbest) k[j] = 0;  // kill
                npop++;
            }

            for (int q = 0; q < npop && nsel < K_; q++) {
                float4 bb;
                bb.x = __shfl_sync(0xffffffffu, myb.x, q);
                bb.y = __shfl_sync(0xffffffffu, myb.y, q);
                bb.z = __shfl_sync(0xffffffffu, myb.z, q);
                bb.w = __shfl_sync(0xffffffffu, myb.w, q);
                float scq = __shfl_sync(0xffffffffu, mysc, q);
                int   nq  = __shfl_sync(0xffffffffu, myn, q);
                bool sup = (lane < nsel) ? sup_iou(bb, selbox[lane]) : false;
                if (!__ballot_sync(0xffffffffu, sup)) {
                    if (lane == 0) {
                        selbox[nsel] = bb; selsc[nsel] = scq; sel_n[nsel] = nq;
                    }
                    nsel++;
                    __syncwarp();
                }
            }
        }

        // ---- exact fallback (probability ~0 on this data) ----
        if (nsel < K_) {
            const float* scp = scores + (size_t)b * N_ * C_ + c;
            while (nsel < K_) {
                u64 best = 0;
                for (int n = lane; n < N_; n += 32) {
                    float v = __ldg(scp + (size_t)n * C_);
                    if (v > THR) {
                        bool excl = false;
                        for (int j = 0; j < nsel; j++) if (sel_n[j] == n) excl = true;
                        if (!excl) {
                            float4 bb = __ldg(bxp + n);
                            for (int j = 0; j < nsel; j++)
                                if (sup_iou(bb, selbox[j])) { excl = true; break; }
                        }
                        if (!excl) { u64 kk = mkey(v, n); if (kk > best) best = kk; }
                    }
                }
                #pragma unroll
                for (int off = 16; off > 0; off >>= 1) {
                    u64 ob = __shfl_down_sync(0xffffffffu, best, off);
                    if (ob > best) best = ob;
                }
                best = __shfl_sync(0xffffffffu, best, 0);
                if ((unsigned)(best >> 32) == 0u) break;
                int nn = N_ - (int)(best & 0xffffffffu);
                if (lane == 0) {
                    selbox[nsel] = __ldg(bxp + nn);
                    selsc[nsel]  = __uint_as_float((unsigned)(best >> 32));
                    sel_n[nsel]  = nn;
                }
                nsel++;
                __syncwarp();
            }
        }
        if (lane == 0) sh_nsel = nsel;
    }
    __syncthreads();

    if (tid < K_) {
        int o = blk * K_ + tid;
        int v = (tid < sh_nsel);
        g_sel_score[o] = v ? selsc[tid] : NMS_NEG;   // invalid -> NEG (< THR)
        float4 z = make_float4(0.f, 0.f, 0.f, 0.f);
        g_sel_box[o] = v ? selbox[tid] : z;
    }
    __threadfence();
    __syncthreads();
    if (tid == 0) sh_tick = atomicAdd(&g_done, 1);
    __syncthreads();
    if (sh_tick != NBLK - 1) return;
    __threadfence();

    // ======== fused final top-8 (last block): register-based, warp=batch ====
    {
        const int wb = tid >> 5;              // 8 warps, one batch each
        const int base = wb * C_ * K_;
        // key = (score_bits, 2047-j): max == (max score, lowest flat index j)
        u64 kk[20];
        #pragma unroll
        for (int q = 0; q < 20; q++) {        // j = lane + 32q, coalesced
            int j = lane + (q << 5);
            float v = g_sel_score[base + j];
            kk[q] = (v > THR)
                  ? ((((u64)__float_as_uint(v)) << 32) | (unsigned)(2047 - j))
                  : 0ULL;
        }
        int vcnt = 0;
        for (int k = 0; k < K_; k++) {
            u64 g = kk[0];
            #pragma unroll
            for (int q = 1; q < 20; q++) if (kk[q] > g) g = kk[q];
            unsigned hi = (unsigned)(g >> 32);
            unsigned bh = __reduce_max_sync(0xffffffffu, hi);
            float* ob = out + wb * 32 + k * 4;
            if (bh != 0u) {
                unsigned lo = (hi == bh) ? (unsigned)g : 0u;
                unsigned bl = __reduce_max_sync(0xffffffffu, lo);
                u64 gbest = (((u64)bh) << 32) | bl;
                #pragma unroll
                for (int q = 0; q < 20; q++) if (kk[q] == gbest) kk[q] = 0;
                int j = 2047 - (int)bl;
                if (lane == 0) {
                    float4 bb = g_sel_box[base + j];
                    ob[0] = fminf(fmaxf(bb.x, 0.f), 1.f);
                    ob[1] = fminf(fmaxf(bb.y, 0.f), 1.f);
                    ob[2] = fminf(fmaxf(bb.z, 0.f), 1.f);
                    ob[3] = fminf(fmaxf(bb.w, 0.f), 1.f);
                    out[B_ * 32 + wb * 8 + k] = __uint_as_float(bh);
                    out[B_ * 40 + wb * 8 + k] = (float)(j >> 3);   // class = j // K
                }
                vcnt++;
            } else if (lane == 0) {
                ob[0] = ob[1] = ob[2] = ob[3] = 0.f;
                out[B_ * 32 + wb * 8 + k] = 0.f;
                out[B_ * 40 + wb * 8 + k] = 0.f;
            }
        }
        if (lane == 0) out[B_ * 48 + wb] = (float)vcnt;
    }
    __syncthreads();
    if (tid == 0) {                       // self-clean for next graph replay
        g_done = 0;
        #pragma unroll
        for (int i = 0; i < B_; i++) g_barrier[i * 32] = 0;
    }
}

extern "C" void kernel_launch(void* const* d_in, const int* in_sizes, int n_in,
                              void* d_out, int out_size)
{
    const float* boxes  = (const float*)d_in[0];
    const float* scores = (const float*)d_in[1];
    if (n_in >= 2 && in_sizes[0] > in_sizes[1]) {   // defensive input order
        const float* t = boxes; boxes = scores; scores = t;
    }
    nms_all<<<NBLK, 256>>>(boxes, scores, (float*)d_out);
}

// round 12
// speedup vs baseline: 1.0923x; 1.0472x over previous
#include <cuda_runtime.h>
#include <cstdint>

#define B_ 8
#define N_ 10000
#define C_ 80
#define K_ 8
#define THR 0.5f
#define T2  0.99f            // collection threshold: ~100 candidates/class
#define NMS_NEG -1e9f
#define CAP 256
#define NBLK (B_ * C_)       // 640

typedef unsigned long long u64;

// Scratch (allocation-free rule: __device__ globals; zero-initialized; every
// counter is restored to zero within the launch => graph-replay deterministic)
__device__ u64    g_cand[NBLK * CAP];
__device__ int    g_ccnt[NBLK * 32];      // 128B stride per counter (atomics)
__device__ float  g_sel_score[NBLK * K_];
__device__ float4 g_sel_box  [NBLK * K_];
__device__ int    g_barrier[B_ * 32];     // arrive counters, 128B stride
__device__ int    g_exit   [B_ * 32];     // exit counters (barrier recycling)
__device__ int    g_tick   [B_ * 32];     // phase-B completion tickets

// key = (score_bits, N-n): max-key == (max score, lowest n). Valid scores are
// positive floats (uint order == float order); 0 = empty sentinel.
__device__ __forceinline__ u64 mkey(float v, int n) {
    return (((u64)__float_as_uint(v)) << 32) | (unsigned)(N_ - n);
}

__device__ __forceinline__ bool sup_iou(float4 a, float4 q) {
    float ih = fmaxf(fminf(a.z, q.z) - fmaxf(a.x, q.x), 0.0f);
    float iw = fmaxf(fminf(a.w, q.w) - fmaxf(a.y, q.y), 0.0f);
    float inter = ih * iw;
    float uni = (a.z - a.x) * (a.w - a.y) + (q.z - q.x) * (q.w - q.y) - inter;
    return inter / fmaxf(uni, 1e-9f) > 0.5f;
}

// ---------------------------------------------------------------------------
// ONE kernel, grid 640 x 256 thr, __launch_bounds__(256,5): all blocks are
// wave-1 resident (148*5=740 >= 640) so the spin barrier cannot deadlock.
//  Phase A: block (b,c) streams rows [125c,125c+125) of batch b (40KB
//           coalesced, __ldg keeps scores L2-resident across graph replays);
//           appends keys >T2 per class.
//  Barrier: PER-BATCH arrive+spin (80), recycled via an exit counter (the
//           80th exiter resets both; nobody reads them again this launch).
//  Phase B: warp-0 register greedy NMS over <=256 keys.
//  Ticket:  PER-BATCH — the 80th phase-B finisher of batch b runs batch b's
//           register top-8 immediately (8 concurrent topks, no global sync).
// Output (f32): boxes[8][8][4] | scores[8][8] | classes[8][8] | valid[8]
// ---------------------------------------------------------------------------
__global__ __launch_bounds__(256, 5) void nms_all(
    const float* __restrict__ boxes, const float* __restrict__ scores,
    float* __restrict__ out)
{
    __shared__ float4 selbox[K_];
    __shared__ float  selsc[K_];
    __shared__ int    sel_n[K_];
    __shared__ int    sh_nsel, sh_tick, sh_cnt;

    const int tid  = threadIdx.x;
    const int lane = tid & 31;
    const int blk  = blockIdx.x;
    const int b    = blk / C_;
    const int c    = blk % C_;           // doubles as phase-A slice id

    // ================= Phase A: stream slice + collect =================
    {
        const float4* sp = reinterpret_cast<const float4*>(scores)
                         + (size_t)b * 200000 + c * 2500;
        const int cbase = b * C_;
        #pragma unroll
        for (int k = 0; k < 10; k++) {               // 2500 = 9*256 + 196
            int i = tid + (k << 8);
            if (i < 2500) {
                float4 v = __ldg(sp + i);            // evict-normal: L2-hot
                int n  = c * 125 + i / 20;           // global box row
                int c0 = (i % 20) * 4;               // class of v.x
                if (v.x > T2) { int p = atomicAdd(&g_ccnt[(cbase+c0  )*32], 1); if (p < CAP) g_cand[(cbase+c0  )*CAP+p] = mkey(v.x, n); }
                if (v.y > T2) { int p = atomicAdd(&g_ccnt[(cbase+c0+1)*32], 1); if (p < CAP) g_cand[(cbase+c0+1)*CAP+p] = mkey(v.y, n); }
                if (v.z > T2) { int p = atomicAdd(&g_ccnt[(cbase+c0+2)*32], 1); if (p < CAP) g_cand[(cbase+c0+2)*CAP+p] = mkey(v.z, n); }
                if (v.w > T2) { int p = atomicAdd(&g_ccnt[(cbase+c0+3)*32], 1); if (p < CAP) g_cand[(cbase+c0+3)*CAP+p] = mkey(v.w, n); }
            }
        }
    }
    __syncthreads();

    // ===== per-batch barrier: arrive + plain spin, exit-counter recycling ===
    if (tid == 0) {
        __threadfence();
        atomicAdd(&g_barrier[b * 32], 1);
        volatile int* bp = &g_barrier[b * 32];
        while (*bp < C_) { }
        __threadfence();                  // acquire
        // recycle: 80th exiter resets both counters (no later readers)
        int ex = atomicAdd(&g_exit[b * 32], 1);
        if (ex == C_ - 1) { g_barrier[b * 32] = 0; g_exit[b * 32] = 0; }
        sh_cnt = g_ccnt[blk * 32];
        g_ccnt[blk * 32] = 0;             // self-clean for next replay
    }
    __syncthreads();

    // ================= Phase B: warp-0 register NMS ====================
    const int  cnt = sh_cnt;
    const int  m   = (cnt > CAP) ? 0 : cnt;   // overflow -> exact fallback

    if (tid < 32) {
        const float4* bxp = reinterpret_cast<const float4*>(boxes) + (size_t)b * N_;

        u64 k[8];
        #pragma unroll
        for (int j = 0; j < 8; j++) {
            int idx = lane + (j << 5);
            k[j] = (idx < m) ? __ldg(&g_cand[blk * CAP + idx]) : 0ULL;
        }

        int  nsel = 0;
        bool exhausted = (m == 0);
        while (nsel < K_ && !exhausted) {
            float4 myb = make_float4(0.f, 0.f, 0.f, 0.f);
            float  mysc = 0.f;
            int    myn  = 0;
            int    npop = 0;
            for (int p = 0; p < 8; p++) {
                u64 g = k[0];
                #pragma unroll
                for (int j = 1; j < 8; j++) if (k[j] > g) g = k[j];
                unsigned hi = (unsigned)(g >> 32);
                unsigned bh = __reduce_max_sync(0xffffffffu, hi);
                if (bh == 0u) { exhausted = true; break; }
                unsigned lo = (hi == bh) ? (unsigned)g : 0u;
                unsigned bl = __reduce_max_sync(0xffffffffu, lo);
                u64 gbest = (((u64)bh) << 32) | bl;
                if (lane == p) {                       // record + prefetch box
                    mysc = __uint_as_float(bh);
                    myn  = N_ - (int)bl;
                    myb  = __ldg(bxp + myn);
                }
                #pragma unroll
                for (int j = 0; j < 8; j++) if (k[j] == gbest) k[j] = 0;  // kill
                npop++;
            }

            for (int q = 0; q < npop && nsel < K_; q++) {
                float4 bb;
                bb.x = __shfl_sync(0xffffffffu, myb.x, q);
                bb.y = __shfl_sync(0xffffffffu, myb.y, q);
                bb.z = __shfl_sync(0xffffffffu, myb.z, q);
                bb.w = __shfl_sync(0xffffffffu, myb.w, q);
                float scq = __shfl_sync(0xffffffffu, mysc, q);
                int   nq  = __shfl_sync(0xffffffffu, myn, q);
                bool sup = (lane < nsel) ? sup_iou(bb, selbox[lane]) : false;
                if (!__ballot_sync(0xffffffffu, sup)) {
                    if (lane == 0) {
                        selbox[nsel] = bb; selsc[nsel] = scq; sel_n[nsel] = nq;
                    }
                    nsel++;
                    __syncwarp();
                }
            }
        }

        // ---- exact fallback (probability ~0 on this data) ----
        if (nsel < K_) {
            const float* scp = scores + (size_t)b * N_ * C_ + c;
            while (nsel < K_) {
                u64 best = 0;
                for (int n = lane; n < N_; n += 32) {
                    float v = __ldg(scp + (size_t)n * C_);
                    if (v > THR) {
                        bool excl = false;
                        for (int j = 0; j < nsel; j++) if (sel_n[j] == n) excl = true;
                        if (!excl) {
                            float4 bb = __ldg(bxp + n);
                            for (int j = 0; j < nsel; j++)
                                if (sup_iou(bb, selbox[j])) { excl = true; break; }
                        }
                        if (!excl) { u64 kk = mkey(v, n); if (kk > best) best = kk; }
                    }
                }
                #pragma unroll
                for (int off = 16; off > 0; off >>= 1) {
                    u64 ob = __shfl_down_sync(0xffffffffu, best, off);
                    if (ob > best) best = ob;
                }
                best = __shfl_sync(0xffffffffu, best, 0);
                if ((unsigned)(best >> 32) == 0u) break;
                int nn = N_ - (int)(best & 0xffffffffu);
                if (lane == 0) {
                    selbox[nn >= 0 ? nsel : nsel] = __ldg(bxp + nn);
                    selsc[nsel]  = __uint_as_float((unsigned)(best >> 32));
                    sel_n[nsel]  = nn;
                }
                nsel++;
                __syncwarp();
            }
        }
        if (lane == 0) sh_nsel = nsel;
    }
    __syncthreads();

    if (tid < K_) {
        int o = blk * K_ + tid;
        int v = (tid < sh_nsel);
        g_sel_score[o] = v ? selsc[tid] : NMS_NEG;   // invalid -> NEG (< THR)
        float4 z = make_float4(0.f, 0.f, 0.f, 0.f);
        g_sel_box[o] = v ? selbox[tid] : z;
    }
    __threadfence();
    __syncthreads();
    if (tid == 0) sh_tick = atomicAdd(&g_tick[b * 32], 1);
    __syncthreads();
    if (sh_tick != C_ - 1) return;        // not this batch's last finisher
    __threadfence();                      // acquire: all 80 blocks' g_sel

    // ======== per-batch top-8 (this batch's last block; warp 0 only) ========
    if (tid < 32) {
        const int base = b * C_ * K_;
        // key = (score_bits, 2047-j): max == (max score, lowest flat index j)
        u64 kk[20];
        #pragma unroll
        for (int q = 0; q < 20; q++) {        // j = lane + 32q, coalesced
            int j = lane + (q << 5);
            float v = g_sel_score[base + j];
            kk[q] = (v > THR)
                  ? ((((u64)__float_as_uint(v)) << 32) | (unsigned)(2047 - j))
                  : 0ULL;
        }
        int vcnt = 0;
        for (int k = 0; k < K_; k++) {
            u64 g = kk[0];
            #pragma unroll
            for (int q = 1; q < 20; q++) if (kk[q] > g) g = kk[q];
            unsigned hi = (unsigned)(g >> 32);
            unsigned bh = __reduce_max_sync(0xffffffffu, hi);
            float* ob = out + b * 32 + k * 4;
            if (bh != 0u) {
                unsigned lo = (hi == bh) ? (unsigned)g : 0u;
                unsigned bl = __reduce_max_sync(0xffffffffu, lo);
                u64 gbest = (((u64)bh) << 32) | bl;
                #pragma unroll
                for (int q = 0; q < 20; q++) if (kk[q] == gbest) kk[q] = 0;
                int j = 2047 - (int)bl;
                if (lane == 0) {
                    float4 bb = g_sel_box[base + j];
                    ob[0] = fminf(fmaxf(bb.x, 0.f), 1.f);
                    ob[1] = fminf(fmaxf(bb.y, 0.f), 1.f);
                    ob[2] = fminf(fmaxf(bb.z, 0.f), 1.f);
                    ob[3] = fminf(fmaxf(bb.w, 0.f), 1.f);
                    out[B_ * 32 + b * 8 + k] = __uint_as_float(bh);
                    out[B_ * 40 + b * 8 + k] = (float)(j >> 3);   // class = j // K
                }
                vcnt++;
            } else if (lane == 0) {
                ob[0] = ob[1] = ob[2] = ob[3] = 0.f;
                out[B_ * 32 + b * 8 + k] = 0.f;
                out[B_ * 40 + b * 8 + k] = 0.f;
            }
        }
        if (lane == 0) {
            out[B_ * 48 + b] = (float)vcnt;
            g_tick[b * 32] = 0;           // self-clean (no later readers)
        }
    }
}

extern "C" void kernel_launch(void* const* d_in, const int* in_sizes, int n_in,
                              void* d_out, int out_size)
{
    const float* boxes  = (const float*)d_in[0];
    const float* scores = (const float*)d_in[1];
    if (n_in >= 2 && in_sizes[0] > in_sizes[1]) {   // defensive input order
        const float* t = boxes; boxes = scores; scores = t;
    }
    nms_all<<<NBLK, 256>>>(boxes, scores, (float*)d_out);
}

// round 13
// speedup vs baseline: 1.3238x; 1.2120x over previous
#include <cuda_runtime.h>
#include <cstdint>

#define B_ 8
#define N_ 10000
#define C_ 80
#define K_ 8
#define THR 0.5f
#define T2  0.99f            // collection threshold: ~100 candidates/class
#define NMS_NEG -1e9f
#define CAP 256
#define NBLK (B_ * C_)       // 640
#define TOT4 1600000         // B*N*C/4 float4 total

typedef unsigned long long u64;

// Scratch (allocation-free rule: __device__ globals; zero-initialized; every
// counter is restored to zero within the launch => graph-replay deterministic)
__device__ u64    g_cand[NBLK * CAP];
__device__ int    g_ccnt[NBLK * 32];      // 128B stride per counter (atomics)
__device__ float  g_sel_score[NBLK * K_];
__device__ float4 g_sel_box  [NBLK * K_];
__device__ int    g_tick[B_ * 32];        // per-batch completion tickets

// key = (score_bits, N-n): max-key == (max score, lowest n). Valid scores are
// positive floats (uint order == float order); 0 = empty sentinel.
__device__ __forceinline__ u64 mkey(float v, int n) {
    return (((u64)__float_as_uint(v)) << 32) | (unsigned)(N_ - n);
}

__device__ __forceinline__ bool sup_iou(float4 a, float4 q) {
    float ih = fmaxf(fminf(a.z, q.z) - fmaxf(a.x, q.x), 0.0f);
    float iw = fmaxf(fminf(a.w, q.w) - fmaxf(a.y, q.y), 0.0f);
    float inter = ih * iw;
    float uni = (a.z - a.x) * (a.w - a.y) + (q.z - q.x) * (q.w - q.y) - inter;
    return inter / fmaxf(uni, 1e-9f) > 0.5f;
}

// ---------------------------------------------------------------------------
// Kernel 1: pure streaming collect. No smem, no sync, lean regs => 8 blocks/SM
// = 2048 threads/SM (full occupancy). Flat index over all B*N*C/4 float4;
// values > T2 append (score, n) keys to their (b,class) candidate list.
// ---------------------------------------------------------------------------
__global__ __launch_bounds__(256) void collect(const float* __restrict__ scores)
{
    const float4* sp = reinterpret_cast<const float4*>(scores);
    const unsigned base = blockIdx.x * 1024u + threadIdx.x;
    #pragma unroll
    for (int k = 0; k < 4; k++) {
        unsigned idx4 = base + (k << 8);
        if (idx4 < TOT4) {
            float4 v = __ldg(sp + idx4);
            unsigned b  = idx4 / 200000u;            // batch
            unsigned r  = idx4 - b * 200000u;
            unsigned n  = r / 20u;                   // box row
            unsigned c0 = (r - n * 20u) << 2;        // class of v.x
            unsigned cb = b * C_ + c0;
            if (v.x > T2) { int p = atomicAdd(&g_ccnt[(cb  )*32], 1); if (p < CAP) g_cand[(cb  )*CAP+p] = mkey(v.x, (int)n); }
            if (v.y > T2) { int p = atomicAdd(&g_ccnt[(cb+1)*32], 1); if (p < CAP) g_cand[(cb+1)*CAP+p] = mkey(v.y, (int)n); }
            if (v.z > T2) { int p = atomicAdd(&g_ccnt[(cb+2)*32], 1); if (p < CAP) g_cand[(cb+2)*CAP+p] = mkey(v.z, (int)n); }
            if (v.w > T2) { int p = atomicAdd(&g_ccnt[(cb+3)*32], 1); if (p < CAP) g_cand[(cb+3)*CAP+p] = mkey(v.w, (int)n); }
        }
    }
}

// ---------------------------------------------------------------------------
// Kernel 2: 640 blocks x 32 threads (one warp; zero block barriers).
//  - register greedy NMS over <=256 keys (redux pops, batched box prefetch,
//    warp-parallel IoU); exact fallback if thin/overflow (probability ~0).
//  - per-batch ticket: the 80th finisher of batch b runs batch b's register
//    top-8 immediately (8 concurrent topks).
// Output (f32): boxes[8][8][4] | scores[8][8] | classes[8][8] | valid[8]
// ---------------------------------------------------------------------------
__global__ __launch_bounds__(32) void nms_finish(
    const float* __restrict__ boxes, const float* __restrict__ scores,
    float* __restrict__ out)
{
    __shared__ float4 selbox[K_];
    __shared__ float  selsc[K_];
    __shared__ int    sel_n[K_];

    const int lane = threadIdx.x;
    const int blk  = blockIdx.x;
    const int b    = blk / C_;
    const int c    = blk % C_;

    int cnt = 0;
    if (lane == 0) { cnt = g_ccnt[blk * 32]; g_ccnt[blk * 32] = 0; }  // self-clean
    cnt = __shfl_sync(0xffffffffu, cnt, 0);
    const int m = (cnt > CAP) ? 0 : cnt;      // overflow -> exact fallback

    const float4* bxp = reinterpret_cast<const float4*>(boxes) + (size_t)b * N_;

    u64 k[8];
    #pragma unroll
    for (int j = 0; j < 8; j++) {
        int idx = lane + (j << 5);
        k[j] = (idx < m) ? __ldg(&g_cand[blk * CAP + idx]) : 0ULL;
    }

    int  nsel = 0;
    bool exhausted = (m == 0);
    while (nsel < K_ && !exhausted) {
        float4 myb = make_float4(0.f, 0.f, 0.f, 0.f);
        float  mysc = 0.f;
        int    myn  = 0;
        int    npop = 0;
        for (int p = 0; p < 8; p++) {
            u64 g = k[0];
            #pragma unroll
            for (int j = 1; j < 8; j++) if (k[j] > g) g = k[j];
            unsigned hi = (unsigned)(g >> 32);
            unsigned bh = __reduce_max_sync(0xffffffffu, hi);
            if (bh == 0u) { exhausted = true; break; }
            unsigned lo = (hi == bh) ? (unsigned)g : 0u;
            unsigned bl = __reduce_max_sync(0xffffffffu, lo);
            u64 gbest = (((u64)bh) << 32) | bl;
            if (lane == p) {                       // record + prefetch box
                mysc = __uint_as_float(bh);
                myn  = N_ - (int)bl;
                myb  = __ldg(bxp + myn);
            }
            #pragma unroll
            for (int j = 0; j < 8; j++) if (k[j] == gbest) k[j] = 0;  // kill
            npop++;
        }

        for (int q = 0; q < npop && nsel < K_; q++) {
            float4 bb;
            bb.x = __shfl_sync(0xffffffffu, myb.x, q);
            bb.y = __shfl_sync(0xffffffffu, myb.y, q);
            bb.z = __shfl_sync(0xffffffffu, myb.z, q);
            bb.w = __shfl_sync(0xffffffffu, myb.w, q);
            float scq = __shfl_sync(0xffffffffu, mysc, q);
            int   nq  = __shfl_sync(0xffffffffu, myn, q);
            bool sup = (lane < nsel) ? sup_iou(bb, selbox[lane]) : false;
            if (!__ballot_sync(0xffffffffu, sup)) {
                if (lane == 0) {
                    selbox[nsel] = bb; selsc[nsel] = scq; sel_n[nsel] = nq;
                }
                nsel++;
                __syncwarp();
            }
        }
    }

    // ---- exact fallback (probability ~0 on this data) ----
    if (nsel < K_) {
        const float* scp = scores + (size_t)b * N_ * C_ + c;
        while (nsel < K_) {
            u64 best = 0;
            for (int n = lane; n < N_; n += 32) {
                float v = __ldg(scp + (size_t)n * C_);
                if (v > THR) {
                    bool excl = false;
                    for (int j = 0; j < nsel; j++) if (sel_n[j] == n) excl = true;
                    if (!excl) {
                        float4 bb = __ldg(bxp + n);
                        for (int j = 0; j < nsel; j++)
                            if (sup_iou(bb, selbox[j])) { excl = true; break; }
                    }
                    if (!excl) { u64 kk = mkey(v, n); if (kk > best) best = kk; }
                }
            }
            #pragma unroll
            for (int off = 16; off > 0; off >>= 1) {
                u64 ob = __shfl_down_sync(0xffffffffu, best, off);
                if (ob > best) best = ob;
            }
            best = __shfl_sync(0xffffffffu, best, 0);
            if ((unsigned)(best >> 32) == 0u) break;
            int nn = N_ - (int)(best & 0xffffffffu);
            if (lane == 0) {
                selbox[nsel] = __ldg(bxp + nn);
                selsc[nsel]  = __uint_as_float((unsigned)(best >> 32));
                sel_n[nsel]  = nn;
            }
            nsel++;
            __syncwarp();
        }
    }

    // ---- publish results for this (b,c) ----
    if (lane < K_) {
        int o = blk * K_ + lane;
        int v = (lane < nsel);
        g_sel_score[o] = v ? selsc[lane] : NMS_NEG;   // invalid -> NEG (< THR)
        float4 z = make_float4(0.f, 0.f, 0.f, 0.f);
        g_sel_box[o] = v ? selbox[lane] : z;
    }
    __threadfence();
    __syncwarp();
    int tick = 0;
    if (lane == 0) tick = atomicAdd(&g_tick[b * 32], 1);
    tick = __shfl_sync(0xffffffffu, tick, 0);
    if (tick != C_ - 1) return;           // not this batch's last finisher
    __threadfence();                      // acquire: all 80 blocks' g_sel

    // ======== per-batch top-8 (this batch's last warp) ========
    {
        const int base = b * C_ * K_;
        // key = (score_bits, 2047-j): max == (max score, lowest flat index j)
        u64 kk[20];
        #pragma unroll
        for (int q = 0; q < 20; q++) {        // j = lane + 32q, coalesced
            int j = lane + (q << 5);
            float v = g_sel_score[base + j];
            kk[q] = (v > THR)
                  ? ((((u64)__float_as_uint(v)) << 32) | (unsigned)(2047 - j))
                  : 0ULL;
        }
        int vcnt = 0;
        for (int kx = 0; kx < K_; kx++) {
            u64 g = kk[0];
            #pragma unroll
            for (int q = 1; q < 20; q++) if (kk[q] > g) g = kk[q];
            unsigned hi = (unsigned)(g >> 32);
            unsigned bh = __reduce_max_sync(0xffffffffu, hi);
            float* ob = out + b * 32 + kx * 4;
            if (bh != 0u) {
                unsigned lo = (hi == bh) ? (unsigned)g : 0u;
                unsigned bl = __reduce_max_sync(0xffffffffu, lo);
                u64 gbest = (((u64)bh) << 32) | bl;
                #pragma unroll
                for (int q = 0; q < 20; q++) if (kk[q] == gbest) kk[q] = 0;
                int j = 2047 - (int)bl;
                if (lane == 0) {
                    float4 bb = g_sel_box[base + j];
                    ob[0] = fminf(fmaxf(bb.x, 0.f), 1.f);
                    ob[1] = fminf(fmaxf(bb.y, 0.f), 1.f);
                    ob[2] = fminf(fmaxf(bb.z, 0.f), 1.f);
                    ob[3] = fminf(fmaxf(bb.w, 0.f), 1.f);
                    out[B_ * 32 + b * 8 + kx] = __uint_as_float(bh);
                    out[B_ * 40 + b * 8 + kx] = (float)(j >> 3);   // class = j // K
                }
                vcnt++;
            } else if (lane == 0) {
                ob[0] = ob[1] = ob[2] = ob[3] = 0.f;
                out[B_ * 32 + b * 8 + kx] = 0.f;
                out[B_ * 40 + b * 8 + kx] = 0.f;
            }
        }
        if (lane == 0) {
            out[B_ * 48 + b] = (float)vcnt;
            g_tick[b * 32] = 0;           // self-clean (no later readers)
        }
    }
}

extern "C" void kernel_launch(void* const* d_in, const int* in_sizes, int n_in,
                              void* d_out, int out_size)
{
    const float* boxes  = (const float*)d_in[0];
    const float* scores = (const float*)d_in[1];
    if (n_in >= 2 && in_sizes[0] > in_sizes[1]) {   // defensive input order
        const float* t = boxes; boxes = scores; scores = t;
    }
    collect<<<(TOT4 + 1023) / 1024, 256>>>(scores);          // 1563 blocks
    nms_finish<<<NBLK, 32>>>(boxes, scores, (float*)d_out);
}